// round 10
// baseline (speedup 1.0000x reference)
#include <cuda_runtime.h>
#include <math.h>

#define DD     2048
#define NS     16
#define BB     2
#define LL     4096
#define NCHAN  (BB * DD)
#define CHUNK  (LL / 32)

__device__ int g_ctr;

__global__ void reset_ctr_kernel() { g_ctr = 0; }

__device__ __forceinline__ float sigm(float v) {
    return 1.0f / (1.0f + expf(-v));
}

__global__ __launch_bounds__(128, 3) void cema_kernel(
    const float* __restrict__ x,      // (B, D, L)
    const float* __restrict__ alpha,  // (D, N)
    const float* __restrict__ delta,  // (D, N)
    const float* __restrict__ theta,  // (D)
    const float* __restrict__ gamma,  // (D, N, 2)
    const float* __restrict__ omega,  // (D)
    float* __restrict__ out)          // y (B,D,L) then h (B,D,N,2)
{
    const int lane = threadIdx.x & 31;

    for (;;) {
        // ---- dynamic channel grab (warp-granular work queue) ----
        int ch;
        if (lane == 0) ch = atomicAdd(&g_ctr, 1);
        ch = __shfl_sync(0xFFFFFFFFu, ch, 0);
        if (ch >= NCHAN) break;
        const int d = ch & (DD - 1);

        const float base = sigm(theta[d]) * (6.283185307179586f / 16.0f);
        const float om   = omega[d];

        // ---- biquad denominator coeffs: a1 = 2*Re(q), a2 = -|q|^2.
        //      qsign bit n = 1 iff sin(phi_n) < 0. ----
        float A1[NS], A2[NS];
        unsigned qsign = 0u;
        #pragma unroll
        for (int n = 0; n < NS; n++) {
            float p   = sigm(alpha[d * NS + n]);
            float de  = sigm(delta[d * NS + n]);
            float mag = 1.0f - p * de;
            float s, c;
            sincosf((float)(n + 1) * base, &s, &c);
            if (s < 0.0f) qsign |= (1u << n);
            A1[n] = 2.0f * (mag * c);
            A2[n] = -(mag * mag);
        }

        const size_t chbase = (size_t)ch * LL;
        const float4* __restrict__ xc4 =
            (const float4*)(x + chbase + (size_t)lane * CHUNK);

        // ---- Phase 1: local biquad scan from zero (W=w[t], Wp=w[t-1]),
        //      8 steps/iter, 2-deep float4 prefetch ----
        float W[NS], Wp[NS];
        #pragma unroll
        for (int n = 0; n < NS; n++) { W[n] = 0.0f; Wp[n] = 0.0f; }

        {
            float4 c0 = xc4[0], c1 = xc4[1];
            #pragma unroll 1
            for (int i = 0; i < 16; i++) {
                int j = (i < 15) ? 2 * i + 2 : 30;
                float4 n0 = xc4[j], n1 = xc4[j + 1];
                float xs[8] = { c0.x, c0.y, c0.z, c0.w, c1.x, c1.y, c1.z, c1.w };
                #pragma unroll
                for (int k = 0; k < 8; k++) {
                    float xk = xs[k];
                    #pragma unroll
                    for (int n = 0; n < NS; n++) {
                        float wn = fmaf(A1[n], W[n], fmaf(A2[n], Wp[n], xk));
                        Wp[n] = W[n]; W[n] = wn;
                    }
                }
                c0 = n0; c1 = n1;
            }
        }

        // ---- chunk transition + warp scan, mode groups of 4
        //      (16 live M-registers, peak-register control) ----
        #pragma unroll
        for (int g = 0; g < 4; g++) {
            float m00[4], m01[4], m10[4], m11[4];
            #pragma unroll
            for (int u = 0; u < 4; u++) {
                int n = 4 * g + u;
                m00[u] = A1[n]; m01[u] = A2[n]; m10[u] = 1.0f; m11[u] = 0.0f;
            }
            #pragma unroll
            for (int s = 0; s < 7; s++) {
                #pragma unroll
                for (int u = 0; u < 4; u++) {
                    float tr = m00[u] + m11[u];
                    float t  = m01[u] * m10[u];
                    float n00 = fmaf(m00[u], m00[u], t);
                    float n11 = fmaf(m11[u], m11[u], t);
                    m01[u] *= tr; m10[u] *= tr;
                    m00[u] = n00; m11[u] = n11;
                }
            }
            #pragma unroll
            for (int k = 1; k <= 16; k <<= 1) {
                #pragma unroll
                for (int u = 0; u < 4; u++) {
                    int n = 4 * g + u;
                    float tw  = __shfl_up_sync(0xFFFFFFFFu, W[n],  k);
                    float twp = __shfl_up_sync(0xFFFFFFFFu, Wp[n], k);
                    if (lane >= k) {
                        float nw = fmaf(m00[u], tw, fmaf(m01[u], twp, W[n]));
                        float np = fmaf(m10[u], tw, fmaf(m11[u], twp, Wp[n]));
                        W[n] = nw; Wp[n] = np;
                    }
                }
                if (k < 16) {
                    #pragma unroll
                    for (int u = 0; u < 4; u++) {
                        float tr = m00[u] + m11[u];
                        float t  = m01[u] * m10[u];
                        float n00 = fmaf(m00[u], m00[u], t);
                        float n11 = fmaf(m11[u], m11[u], t);
                        m01[u] *= tr; m10[u] *= tr;
                        m00[u] = n00; m11[u] = n11;
                    }
                }
            }
        }

        // ---- h from lane 31 ----
        if (lane == 31) {
            float* hptr = out + (size_t)BB * DD * LL + (size_t)ch * NS * 2;
            #pragma unroll
            for (int n = 0; n < NS; n++) {
                float qr = 0.5f * A1[n];
                float qi = sqrtf(fmaxf(fmaf(-qr, qr, -A2[n]), 0.0f));
                if (qsign & (1u << n)) qi = -qi;
                float p  = sigm(alpha[d * NS + n]);
                hptr[2 * n + 0] = p * fmaf(-qr, Wp[n], W[n]);
                hptr[2 * n + 1] = p * (qi * Wp[n]);
            }
        }

        // ---- incoming state per chunk = exclusive scan (shift by 1) ----
        #pragma unroll
        for (int n = 0; n < NS; n++) {
            float tw  = __shfl_up_sync(0xFFFFFFFFu, W[n],  1);
            float twp = __shfl_up_sync(0xFFFFFFFFu, Wp[n], 1);
            W[n]  = (lane == 0) ? 0.0f : tw;
            Wp[n] = (lane == 0) ? 0.0f : twp;
        }

        // ---- numerator coeffs: b0 = Re(c), b1 = -Re(c*conj(q)) ----
        float B0[NS], B1[NS];
        #pragma unroll
        for (int n = 0; n < NS; n++) {
            float qr = 0.5f * A1[n];
            float qi = sqrtf(fmaxf(fmaf(-qr, qr, -A2[n]), 0.0f));
            if (qsign & (1u << n)) qi = -qi;
            float p  = sigm(alpha[d * NS + n]);
            float cr = p * gamma[(d * NS + n) * 2 + 0] * 0.25f;
            float ci = p * gamma[(d * NS + n) * 2 + 1] * 0.25f;
            B0[n] = cr;
            B1[n] = -fmaf(cr, qr, ci * qi);
        }

        // ---- Phase 2: rescan with correct init, emit y ----
        float4* __restrict__ yc4 = (float4*)(out + chbase + (size_t)lane * CHUNK);
        {
            float4 c0 = xc4[0], c1 = xc4[1];
            #pragma unroll 1
            for (int i = 0; i < 16; i++) {
                int j = (i < 15) ? 2 * i + 2 : 30;
                float4 n0 = xc4[j], n1 = xc4[j + 1];
                float xs[8] = { c0.x, c0.y, c0.z, c0.w, c1.x, c1.y, c1.z, c1.w };
                float ys[8];
                #pragma unroll
                for (int k = 0; k < 8; k++) {
                    float xk = xs[k];
                    float acc0 = xk * om;
                    float acc1 = 0.0f, acc2 = 0.0f, acc3 = 0.0f;
                    #pragma unroll
                    for (int n = 0; n < NS; n++) {
                        float wn = fmaf(A1[n], W[n], fmaf(A2[n], Wp[n], xk));
                        float& acc = (n & 3) == 0 ? acc0 : (n & 3) == 1 ? acc1
                                   : (n & 3) == 2 ? acc2 : acc3;
                        acc = fmaf(B0[n], wn,   acc);
                        acc = fmaf(B1[n], W[n], acc);
                        Wp[n] = W[n]; W[n] = wn;
                    }
                    ys[k] = (acc0 + acc1) + (acc2 + acc3);
                }
                yc4[2 * i + 0] = make_float4(ys[0], ys[1], ys[2], ys[3]);
                yc4[2 * i + 1] = make_float4(ys[4], ys[5], ys[6], ys[7]);
                c0 = n0; c1 = n1;
            }
        }
    }
}

extern "C" void kernel_launch(void* const* d_in, const int* in_sizes, int n_in,
                              void* d_out, int out_size)
{
    const float* x     = (const float*)d_in[0];
    const float* alpha = (const float*)d_in[1];
    const float* delta = (const float*)d_in[2];
    const float* theta = (const float*)d_in[3];
    const float* gamma = (const float*)d_in[4];
    const float* omega = (const float*)d_in[5];
    float* out = (float*)d_out;

    reset_ctr_kernel<<<1, 1>>>();
    // Persistent grid: 3 CTAs/SM x 152 SMs; warps pull channels dynamically.
    cema_kernel<<<456, 128>>>(x, alpha, delta, theta, gamma, omega, out);
}

// round 12
// speedup vs baseline: 1.2738x; 1.2738x over previous
#include <cuda_runtime.h>
#include <math.h>

#define DD     2048
#define NS     16
#define BB     2
#define LL     4096
#define NCHAN  (BB * DD)
#define CHUNK  (LL / 32)

__device__ int g_ctr;

__global__ void reset_ctr_kernel() { g_ctr = 0; }

// fast sigmoid: MUFU ex2-based exp + fast reciprocal. abs err ~1e-6, fine here.
__device__ __forceinline__ float sigm(float v) {
    return __fdividef(1.0f, 1.0f + __expf(-v));
}

__global__ __launch_bounds__(128, 4) void cema_kernel(
    const float* __restrict__ x,      // (B, D, L)
    const float* __restrict__ alpha,  // (D, N)
    const float* __restrict__ delta,  // (D, N)
    const float* __restrict__ theta,  // (D)
    const float* __restrict__ gamma,  // (D, N, 2)
    const float* __restrict__ omega,  // (D)
    float* __restrict__ out)          // y (B,D,L) then h (B,D,N,2)
{
    const int lane = threadIdx.x & 31;

    for (;;) {
        // ---- dynamic channel grab (warp-granular work queue) ----
        int ch;
        if (lane == 0) ch = atomicAdd(&g_ctr, 1);
        ch = __shfl_sync(0xFFFFFFFFu, ch, 0);
        if (ch >= NCHAN) break;
        const int d = ch & (DD - 1);

        const float base = sigm(theta[d]) * (6.283185307179586f / 16.0f);
        const float om   = omega[d];

        // ---- biquad denominator coeffs: a1 = 2*Re(q), a2 = -|q|^2.
        //      qsign bit n = 1 iff sin(phi_n) < 0. ----
        float A1[NS], A2[NS];
        unsigned qsign = 0u;
        #pragma unroll
        for (int n = 0; n < NS; n++) {
            float p   = sigm(alpha[d * NS + n]);
            float de  = sigm(delta[d * NS + n]);
            float mag = 1.0f - p * de;
            float s, c;
            __sincosf((float)(n + 1) * base, &s, &c);
            if (s < 0.0f) qsign |= (1u << n);
            A1[n] = 2.0f * (mag * c);
            A2[n] = -(mag * mag);
        }

        const size_t chbase = (size_t)ch * LL;
        const float4* __restrict__ xbase =
            (const float4*)(x + chbase + (size_t)lane * CHUNK);

        // ---- Phase 1: local biquad scan from zero (W=w[t], Wp=w[t-1]),
        //      8 steps/iter, 2-deep float4 prefetch (MLP=2) ----
        float W[NS], Wp[NS];
        #pragma unroll
        for (int n = 0; n < NS; n++) { W[n] = 0.0f; Wp[n] = 0.0f; }

        {
            const float4* xp = xbase;
            float4 c0 = xp[0], c1 = xp[1];
            #pragma unroll 1
            for (int i = 0; i < 16; i++) {
                const float4* np = (i < 15) ? (xp + 2) : xbase;
                float4 n0 = np[0], n1 = np[1];
                float xs[8] = { c0.x, c0.y, c0.z, c0.w, c1.x, c1.y, c1.z, c1.w };
                #pragma unroll
                for (int k = 0; k < 8; k++) {
                    float xk = xs[k];
                    #pragma unroll
                    for (int n = 0; n < NS; n++) {
                        float wn = fmaf(A1[n], W[n], fmaf(A2[n], Wp[n], xk));
                        Wp[n] = W[n]; W[n] = wn;
                    }
                }
                c0 = n0; c1 = n1; xp = np;
            }
        }

        // ---- chunk transition + warp scan, mode groups of 4
        //      (16 live M-registers, peak-register control) ----
        #pragma unroll
        for (int g = 0; g < 4; g++) {
            float m00[4], m01[4], m10[4], m11[4];
            #pragma unroll
            for (int u = 0; u < 4; u++) {
                int n = 4 * g + u;
                m00[u] = A1[n]; m01[u] = A2[n]; m10[u] = 1.0f; m11[u] = 0.0f;
            }
            #pragma unroll
            for (int s = 0; s < 7; s++) {
                #pragma unroll
                for (int u = 0; u < 4; u++) {
                    float tr = m00[u] + m11[u];
                    float t  = m01[u] * m10[u];
                    float n00 = fmaf(m00[u], m00[u], t);
                    float n11 = fmaf(m11[u], m11[u], t);
                    m01[u] *= tr; m10[u] *= tr;
                    m00[u] = n00; m11[u] = n11;
                }
            }
            #pragma unroll
            for (int k = 1; k <= 16; k <<= 1) {
                #pragma unroll
                for (int u = 0; u < 4; u++) {
                    int n = 4 * g + u;
                    float tw  = __shfl_up_sync(0xFFFFFFFFu, W[n],  k);
                    float twp = __shfl_up_sync(0xFFFFFFFFu, Wp[n], k);
                    if (lane >= k) {
                        float nw = fmaf(m00[u], tw, fmaf(m01[u], twp, W[n]));
                        float np = fmaf(m10[u], tw, fmaf(m11[u], twp, Wp[n]));
                        W[n] = nw; Wp[n] = np;
                    }
                }
                if (k < 16) {
                    #pragma unroll
                    for (int u = 0; u < 4; u++) {
                        float tr = m00[u] + m11[u];
                        float t  = m01[u] * m10[u];
                        float n00 = fmaf(m00[u], m00[u], t);
                        float n11 = fmaf(m11[u], m11[u], t);
                        m01[u] *= tr; m10[u] *= tr;
                        m00[u] = n00; m11[u] = n11;
                    }
                }
            }
        }

        // ---- h from lane 31: qr = a1/2, |qi| = sqrt(-a2 - qr^2), sign from qsign ----
        if (lane == 31) {
            float* hptr = out + (size_t)BB * DD * LL + (size_t)ch * NS * 2;
            #pragma unroll
            for (int n = 0; n < NS; n++) {
                float qr = 0.5f * A1[n];
                float qi = __fsqrt_rn(fmaxf(fmaf(-qr, qr, -A2[n]), 0.0f));
                if (qsign & (1u << n)) qi = -qi;
                float p  = sigm(alpha[d * NS + n]);
                hptr[2 * n + 0] = p * fmaf(-qr, Wp[n], W[n]);
                hptr[2 * n + 1] = p * (qi * Wp[n]);
            }
        }

        // ---- incoming state per chunk = exclusive scan (shift by 1) ----
        #pragma unroll
        for (int n = 0; n < NS; n++) {
            float tw  = __shfl_up_sync(0xFFFFFFFFu, W[n],  1);
            float twp = __shfl_up_sync(0xFFFFFFFFu, Wp[n], 1);
            W[n]  = (lane == 0) ? 0.0f : tw;
            Wp[n] = (lane == 0) ? 0.0f : twp;
        }

        // ---- numerator coeffs: b0 = Re(c), b1 = -Re(c*conj(q)) ----
        float B0[NS], B1[NS];
        #pragma unroll
        for (int n = 0; n < NS; n++) {
            float qr = 0.5f * A1[n];
            float qi = __fsqrt_rn(fmaxf(fmaf(-qr, qr, -A2[n]), 0.0f));
            if (qsign & (1u << n)) qi = -qi;
            float p  = sigm(alpha[d * NS + n]);
            float cr = p * gamma[(d * NS + n) * 2 + 0] * 0.25f;
            float ci = p * gamma[(d * NS + n) * 2 + 1] * 0.25f;
            B0[n] = cr;
            B1[n] = -fmaf(cr, qr, ci * qi);
        }

        // ---- Phase 2: rescan with correct init, emit y ----
        float4* __restrict__ ybase = (float4*)(out + chbase + (size_t)lane * CHUNK);
        {
            const float4* xp = xbase;
            float4* yp = ybase;
            float4 c0 = xp[0], c1 = xp[1];
            #pragma unroll 1
            for (int i = 0; i < 16; i++) {
                const float4* np = (i < 15) ? (xp + 2) : xbase;
                float4 n0 = np[0], n1 = np[1];
                float xs[8] = { c0.x, c0.y, c0.z, c0.w, c1.x, c1.y, c1.z, c1.w };
                float ys[8];
                #pragma unroll
                for (int k = 0; k < 8; k++) {
                    float xk = xs[k];
                    float acc0 = xk * om;
                    float acc1 = 0.0f, acc2 = 0.0f, acc3 = 0.0f;
                    #pragma unroll
                    for (int n = 0; n < NS; n++) {
                        float wn = fmaf(A1[n], W[n], fmaf(A2[n], Wp[n], xk));
                        float& acc = (n & 3) == 0 ? acc0 : (n & 3) == 1 ? acc1
                                   : (n & 3) == 2 ? acc2 : acc3;
                        acc = fmaf(B0[n], wn,   acc);
                        acc = fmaf(B1[n], W[n], acc);
                        Wp[n] = W[n]; W[n] = wn;
                    }
                    ys[k] = (acc0 + acc1) + (acc2 + acc3);
                }
                yp[0] = make_float4(ys[0], ys[1], ys[2], ys[3]);
                yp[1] = make_float4(ys[4], ys[5], ys[6], ys[7]);
                c0 = n0; c1 = n1; xp = np; yp += 2;
            }
        }
    }
}

extern "C" void kernel_launch(void* const* d_in, const int* in_sizes, int n_in,
                              void* d_out, int out_size)
{
    const float* x     = (const float*)d_in[0];
    const float* alpha = (const float*)d_in[1];
    const float* delta = (const float*)d_in[2];
    const float* theta = (const float*)d_in[3];
    const float* gamma = (const float*)d_in[4];
    const float* omega = (const float*)d_in[5];
    float* out = (float*)d_out;

    reset_ctr_kernel<<<1, 1>>>();
    // Persistent grid: 4 CTAs/SM x 152 SMs; warps pull channels dynamically.
    cema_kernel<<<608, 128>>>(x, alpha, delta, theta, gamma, omega, out);
}

// round 13
// speedup vs baseline: 1.4837x; 1.1648x over previous
#include <cuda_runtime.h>
#include <math.h>

#define DD     2048
#define NS     16
#define NP     8               // mode pairs
#define BB     2
#define LL     4096
#define NCHAN  (BB * DD)
#define CHUNK  (LL / 32)

typedef unsigned long long u64;

__device__ int g_ctr;
__global__ void reset_ctr_kernel() { g_ctr = 0; }

__device__ __forceinline__ u64 pk2(float lo, float hi) {
    u64 r; asm("mov.b64 %0, {%1,%2};" : "=l"(r) : "f"(lo), "f"(hi)); return r;
}
__device__ __forceinline__ void upk2(u64 v, float& lo, float& hi) {
    asm("mov.b64 {%0,%1}, %2;" : "=f"(lo), "=f"(hi) : "l"(v));
}
__device__ __forceinline__ u64 ffma2(u64 a, u64 b, u64 c) {
    u64 d; asm("fma.rn.f32x2 %0, %1, %2, %3;" : "=l"(d) : "l"(a), "l"(b), "l"(c)); return d;
}
__device__ __forceinline__ u64 fmul2(u64 a, u64 b) {
    u64 d; asm("mul.rn.f32x2 %0, %1, %2;" : "=l"(d) : "l"(a), "l"(b)); return d;
}
__device__ __forceinline__ u64 fadd2(u64 a, u64 b) {
    u64 d; asm("add.rn.f32x2 %0, %1, %2;" : "=l"(d) : "l"(a), "l"(b)); return d;
}
__device__ __forceinline__ float sigm(float v) {
    return __fdividef(1.0f, 1.0f + __expf(-v));
}

__global__ __launch_bounds__(128, 4) void cema_kernel(
    const float* __restrict__ x,      // (B, D, L)
    const float* __restrict__ alpha,  // (D, N)
    const float* __restrict__ delta,  // (D, N)
    const float* __restrict__ theta,  // (D)
    const float* __restrict__ gamma,  // (D, N, 2)
    const float* __restrict__ omega,  // (D)
    float* __restrict__ out)          // y (B,D,L) then h (B,D,N,2)
{
    const int lane = threadIdx.x & 31;

    for (;;) {
        // ---- dynamic channel grab ----
        int ch;
        if (lane == 0) ch = atomicAdd(&g_ctr, 1);
        ch = __shfl_sync(0xFFFFFFFFu, ch, 0);
        if (ch >= NCHAN) break;
        const int d = ch & (DD - 1);

        const float base = sigm(theta[d]) * (6.283185307179586f / 16.0f);
        const float om   = omega[d];

        // ---- biquad denominator coeffs, packed over mode pairs.
        //      a1 = 2*Re(q), a2 = -|q|^2; qsign bit n = (sin(phi_n) < 0). ----
        u64 A1[NP], A2[NP];
        unsigned qsign = 0u;
        #pragma unroll
        for (int j = 0; j < NP; j++) {
            float a1v[2], a2v[2];
            #pragma unroll
            for (int h = 0; h < 2; h++) {
                int n = 2 * j + h;
                float p   = sigm(alpha[d * NS + n]);
                float de  = sigm(delta[d * NS + n]);
                float mag = 1.0f - p * de;
                float s, c;
                __sincosf((float)(n + 1) * base, &s, &c);
                if (s < 0.0f) qsign |= (1u << n);
                a1v[h] = 2.0f * (mag * c);
                a2v[h] = -(mag * mag);
            }
            A1[j] = pk2(a1v[0], a1v[1]);
            A2[j] = pk2(a2v[0], a2v[1]);
        }

        const size_t chbase = (size_t)ch * LL;
        const float4* __restrict__ xbase =
            (const float4*)(x + chbase + (size_t)lane * CHUNK);

        // ---- Phase 1: local packed biquad scan from zero ----
        u64 W[NP], Wp[NP];
        #pragma unroll
        for (int j = 0; j < NP; j++) { W[j] = 0ull; Wp[j] = 0ull; }

        {
            const float4* xp = xbase;
            float4 c0 = xp[0], c1 = xp[1];
            #pragma unroll 1
            for (int i = 0; i < 16; i++) {
                const float4* np = (i < 15) ? (xp + 2) : xbase;
                float4 n0 = np[0], n1 = np[1];
                float xs[8] = { c0.x, c0.y, c0.z, c0.w, c1.x, c1.y, c1.z, c1.w };
                #pragma unroll
                for (int k = 0; k < 8; k++) {
                    u64 X = pk2(xs[k], xs[k]);
                    #pragma unroll
                    for (int j = 0; j < NP; j++) {
                        u64 wn = ffma2(A1[j], W[j], ffma2(A2[j], Wp[j], X));
                        Wp[j] = W[j]; W[j] = wn;
                    }
                }
                c0 = n0; c1 = n1; xp = np;
            }
        }

        // ---- chunk transition + warp scan, pair groups of 2 (= 4 modes),
        //      16 live M-registers per group ----
        const u64 ONE2 = pk2(1.0f, 1.0f);
        #pragma unroll
        for (int g = 0; g < 4; g++) {
            u64 m00[2], m01[2], m10[2], m11[2];
            #pragma unroll
            for (int u = 0; u < 2; u++) {
                int j = 2 * g + u;
                m00[u] = A1[j]; m01[u] = A2[j]; m10[u] = ONE2; m11[u] = 0ull;
            }
            #pragma unroll
            for (int s = 0; s < 7; s++) {
                #pragma unroll
                for (int u = 0; u < 2; u++) {
                    u64 tr = fadd2(m00[u], m11[u]);
                    u64 t  = fmul2(m01[u], m10[u]);
                    u64 n00 = ffma2(m00[u], m00[u], t);
                    u64 n11 = ffma2(m11[u], m11[u], t);
                    m01[u] = fmul2(m01[u], tr);
                    m10[u] = fmul2(m10[u], tr);
                    m00[u] = n00; m11[u] = n11;
                }
            }
            #pragma unroll
            for (int k = 1; k <= 16; k <<= 1) {
                #pragma unroll
                for (int u = 0; u < 2; u++) {
                    int j = 2 * g + u;
                    u64 tw  = __shfl_up_sync(0xFFFFFFFFu, W[j],  k);
                    u64 twp = __shfl_up_sync(0xFFFFFFFFu, Wp[j], k);
                    if (lane >= k) {
                        u64 nw = ffma2(m00[u], tw, ffma2(m01[u], twp, W[j]));
                        u64 np = ffma2(m10[u], tw, ffma2(m11[u], twp, Wp[j]));
                        W[j] = nw; Wp[j] = np;
                    }
                }
                if (k < 16) {
                    #pragma unroll
                    for (int u = 0; u < 2; u++) {
                        u64 tr = fadd2(m00[u], m11[u]);
                        u64 t  = fmul2(m01[u], m10[u]);
                        u64 n00 = ffma2(m00[u], m00[u], t);
                        u64 n11 = ffma2(m11[u], m11[u], t);
                        m01[u] = fmul2(m01[u], tr);
                        m10[u] = fmul2(m10[u], tr);
                        m00[u] = n00; m11[u] = n11;
                    }
                }
            }
        }

        // ---- h from lane 31 (unpack pairs): qr = a1/2,
        //      |qi| = sqrt(-a2 - qr^2) signed by qsign; h = p * S[L-1] ----
        if (lane == 31) {
            float* hptr = out + (size_t)BB * DD * LL + (size_t)ch * NS * 2;
            #pragma unroll
            for (int j = 0; j < NP; j++) {
                float a1v[2], a2v[2], wv[2], wpv[2];
                upk2(A1[j], a1v[0], a1v[1]);
                upk2(A2[j], a2v[0], a2v[1]);
                upk2(W[j],  wv[0],  wv[1]);
                upk2(Wp[j], wpv[0], wpv[1]);
                #pragma unroll
                for (int h = 0; h < 2; h++) {
                    int n = 2 * j + h;
                    float qr = 0.5f * a1v[h];
                    float qi = __fsqrt_rn(fmaxf(fmaf(-qr, qr, -a2v[h]), 0.0f));
                    if (qsign & (1u << n)) qi = -qi;
                    float p  = sigm(alpha[d * NS + n]);
                    hptr[2 * n + 0] = p * fmaf(-qr, wpv[h], wv[h]);
                    hptr[2 * n + 1] = p * (qi * wpv[h]);
                }
            }
        }

        // ---- incoming state per chunk = exclusive scan (shift by 1) ----
        #pragma unroll
        for (int j = 0; j < NP; j++) {
            u64 tw  = __shfl_up_sync(0xFFFFFFFFu, W[j],  1);
            u64 twp = __shfl_up_sync(0xFFFFFFFFu, Wp[j], 1);
            W[j]  = (lane == 0) ? 0ull : tw;
            Wp[j] = (lane == 0) ? 0ull : twp;
        }

        // ---- numerator coeffs packed: b0 = Re(c), b1 = -Re(c*conj(q)) ----
        u64 B0[NP], B1[NP];
        #pragma unroll
        for (int j = 0; j < NP; j++) {
            float a1v[2], a2v[2], b0v[2], b1v[2];
            upk2(A1[j], a1v[0], a1v[1]);
            upk2(A2[j], a2v[0], a2v[1]);
            #pragma unroll
            for (int h = 0; h < 2; h++) {
                int n = 2 * j + h;
                float qr = 0.5f * a1v[h];
                float qi = __fsqrt_rn(fmaxf(fmaf(-qr, qr, -a2v[h]), 0.0f));
                if (qsign & (1u << n)) qi = -qi;
                float p  = sigm(alpha[d * NS + n]);
                float cr = p * gamma[(d * NS + n) * 2 + 0] * 0.25f;
                float ci = p * gamma[(d * NS + n) * 2 + 1] * 0.25f;
                b0v[h] = cr;
                b1v[h] = -fmaf(cr, qr, ci * qi);
            }
            B0[j] = pk2(b0v[0], b0v[1]);
            B1[j] = pk2(b1v[0], b1v[1]);
        }

        // ---- Phase 2: packed rescan with correct init, emit y ----
        float4* __restrict__ ybase = (float4*)(out + chbase + (size_t)lane * CHUNK);
        {
            const float4* xp = xbase;
            float4* yp = ybase;
            float4 c0 = xp[0], c1 = xp[1];
            #pragma unroll 1
            for (int i = 0; i < 16; i++) {
                const float4* np = (i < 15) ? (xp + 2) : xbase;
                float4 n0 = np[0], n1 = np[1];
                float xs[8] = { c0.x, c0.y, c0.z, c0.w, c1.x, c1.y, c1.z, c1.w };
                float ys[8];
                #pragma unroll
                for (int k = 0; k < 8; k++) {
                    float xk = xs[k];
                    u64 X = pk2(xk, xk);
                    u64 acc0 = pk2(xk * om, 0.0f);
                    u64 acc1 = 0ull;
                    #pragma unroll
                    for (int j = 0; j < NP; j++) {
                        u64 wn = ffma2(A1[j], W[j], ffma2(A2[j], Wp[j], X));
                        u64& acc = (j & 1) ? acc1 : acc0;
                        acc = ffma2(B0[j], wn,   acc);
                        acc = ffma2(B1[j], W[j], acc);
                        Wp[j] = W[j]; W[j] = wn;
                    }
                    u64 s = fadd2(acc0, acc1);
                    float lo, hi;
                    upk2(s, lo, hi);
                    ys[k] = lo + hi;
                }
                yp[0] = make_float4(ys[0], ys[1], ys[2], ys[3]);
                yp[1] = make_float4(ys[4], ys[5], ys[6], ys[7]);
                c0 = n0; c1 = n1; xp = np; yp += 2;
            }
        }
    }
}

extern "C" void kernel_launch(void* const* d_in, const int* in_sizes, int n_in,
                              void* d_out, int out_size)
{
    const float* x     = (const float*)d_in[0];
    const float* alpha = (const float*)d_in[1];
    const float* delta = (const float*)d_in[2];
    const float* theta = (const float*)d_in[3];
    const float* gamma = (const float*)d_in[4];
    const float* omega = (const float*)d_in[5];
    float* out = (float*)d_out;

    reset_ctr_kernel<<<1, 1>>>();
    // Persistent grid: 4 CTAs/SM x 152 SMs; warps pull channels dynamically.
    cema_kernel<<<608, 128>>>(x, alpha, delta, theta, gamma, omega, out);
}

// round 14
// speedup vs baseline: 2.0005x; 1.3484x over previous
#include <cuda_runtime.h>
#include <math.h>

#define DD     2048
#define NS     16
#define NP     8               // mode pairs
#define BB     2
#define LL     4096
#define NCHAN  (BB * DD)
#define CHUNK  (LL / 32)

typedef unsigned long long u64;

__device__ int g_ctr;
__global__ void reset_ctr_kernel() { g_ctr = 0; }

__device__ __forceinline__ u64 pk2(float lo, float hi) {
    u64 r; asm("mov.b64 %0, {%1,%2};" : "=l"(r) : "f"(lo), "f"(hi)); return r;
}
__device__ __forceinline__ void upk2(u64 v, float& lo, float& hi) {
    asm("mov.b64 {%0,%1}, %2;" : "=f"(lo), "=f"(hi) : "l"(v));
}
__device__ __forceinline__ u64 ffma2(u64 a, u64 b, u64 c) {
    u64 d; asm("fma.rn.f32x2 %0, %1, %2, %3;" : "=l"(d) : "l"(a), "l"(b), "l"(c)); return d;
}
__device__ __forceinline__ u64 fadd2(u64 a, u64 b) {
    u64 d; asm("add.rn.f32x2 %0, %1, %2;" : "=l"(d) : "l"(a), "l"(b)); return d;
}
__device__ __forceinline__ float sigm(float v) {
    return __fdividef(1.0f, 1.0f + __expf(-v));
}

__global__ __launch_bounds__(128, 4) void cema_kernel(
    const float* __restrict__ x,      // (B, D, L)
    const float* __restrict__ alpha,  // (D, N)
    const float* __restrict__ delta,  // (D, N)
    const float* __restrict__ theta,  // (D)
    const float* __restrict__ gamma,  // (D, N, 2)
    const float* __restrict__ omega,  // (D)
    float* __restrict__ out)          // y (B,D,L) then h (B,D,N,2)
{
    const int lane = threadIdx.x & 31;

    for (;;) {
        // ---- dynamic channel grab ----
        int ch;
        if (lane == 0) ch = atomicAdd(&g_ctr, 1);
        ch = __shfl_sync(0xFFFFFFFFu, ch, 0);
        if (ch >= NCHAN) break;
        const int d = ch & (DD - 1);

        const float base = sigm(theta[d]) * (6.283185307179586f / 16.0f);
        const float om   = omega[d];

        // ---- all coefficients in one pass (q available from sincos here):
        //      a1 = 2*Re(q), a2 = -|q|^2, b0 = Re(c), b1 = -Re(c*conj(q)).
        //      Track magmax for the adaptive warm-up length. ----
        u64 A1[NP], A2[NP], B0[NP], B1[NP];
        unsigned qsign = 0u;
        float magmax = 0.0f;
        #pragma unroll
        for (int j = 0; j < NP; j++) {
            float a1v[2], a2v[2], b0v[2], b1v[2];
            #pragma unroll
            for (int h = 0; h < 2; h++) {
                int n = 2 * j + h;
                float p   = sigm(alpha[d * NS + n]);
                float de  = sigm(delta[d * NS + n]);
                float mag = 1.0f - p * de;
                magmax = fmaxf(magmax, mag);
                float s, c;
                __sincosf((float)(n + 1) * base, &s, &c);
                if (s < 0.0f) qsign |= (1u << n);
                float qr = mag * c, qi = mag * s;
                a1v[h] = 2.0f * qr;
                a2v[h] = -(mag * mag);
                float cr = p * gamma[(d * NS + n) * 2 + 0] * 0.25f;
                float ci = p * gamma[(d * NS + n) * 2 + 1] * 0.25f;
                b0v[h] = cr;
                b1v[h] = -fmaf(cr, qr, ci * qi);
            }
            A1[j] = pk2(a1v[0], a1v[1]);
            A2[j] = pk2(a2v[0], a2v[1]);
            B0[j] = pk2(b0v[0], b0v[1]);
            B1[j] = pk2(b1v[0], b1v[1]);
        }

        // ---- adaptive warm-up length: magmax^K <= e^-11.5 = 1e-5,
        //      rounded up to a multiple of 8, clamped to [8, 128].
        //      At the clamp, error <= 0.91^128 ~ 6e-6. ----
        int K = (int)ceilf(__fdividef(11.5f, -__logf(magmax)));
        K = min(K, CHUNK);
        K = (K + 7) & ~7;
        K = max(K, 8);
        const int nwu = K >> 3;

        const size_t chbase = (size_t)ch * LL;
        const float4* __restrict__ xbase =
            (const float4*)(x + chbase + (size_t)lane * CHUNK);

        // ---- warm-up: run recurrence over the last K steps of the previous
        //      lane's chunk, from zero state (lane 0: forced to zero after). ----
        u64 W[NP], Wp[NP];
        #pragma unroll
        for (int j = 0; j < NP; j++) { W[j] = 0ull; Wp[j] = 0ull; }

        {
            const float4* wb4 = (lane == 0) ? xbase
                : (const float4*)(x + chbase + (size_t)lane * CHUNK - K);
            const float4* xp = wb4;
            float4 c0 = xp[0], c1 = xp[1];
            #pragma unroll 1
            for (int i = 0; i < nwu; i++) {
                const float4* np = (i + 1 < nwu) ? (xp + 2) : wb4;
                float4 n0 = np[0], n1 = np[1];
                float xs[8] = { c0.x, c0.y, c0.z, c0.w, c1.x, c1.y, c1.z, c1.w };
                #pragma unroll
                for (int k = 0; k < 8; k++) {
                    u64 X = pk2(xs[k], xs[k]);
                    #pragma unroll
                    for (int j = 0; j < NP; j++) {
                        u64 wn = ffma2(A1[j], W[j], ffma2(A2[j], Wp[j], X));
                        Wp[j] = W[j]; W[j] = wn;
                    }
                }
                c0 = n0; c1 = n1; xp = np;
            }
            if (lane == 0) {
                #pragma unroll
                for (int j = 0; j < NP; j++) { W[j] = 0ull; Wp[j] = 0ull; }
            }
        }

        // ---- main pass: 128 steps over own chunk, emit y ----
        float4* __restrict__ ybase = (float4*)(out + chbase + (size_t)lane * CHUNK);
        {
            const float4* xp = xbase;
            float4* yp = ybase;
            float4 c0 = xp[0], c1 = xp[1];
            #pragma unroll 1
            for (int i = 0; i < 16; i++) {
                const float4* np = (i < 15) ? (xp + 2) : xbase;
                float4 n0 = np[0], n1 = np[1];
                float xs[8] = { c0.x, c0.y, c0.z, c0.w, c1.x, c1.y, c1.z, c1.w };
                float ys[8];
                #pragma unroll
                for (int k = 0; k < 8; k++) {
                    float xk = xs[k];
                    u64 X = pk2(xk, xk);
                    u64 acc0 = pk2(xk * om, 0.0f);
                    u64 acc1 = 0ull;
                    #pragma unroll
                    for (int j = 0; j < NP; j++) {
                        u64 wn = ffma2(A1[j], W[j], ffma2(A2[j], Wp[j], X));
                        u64& acc = (j & 1) ? acc1 : acc0;
                        acc = ffma2(B0[j], wn,   acc);
                        acc = ffma2(B1[j], W[j], acc);
                        Wp[j] = W[j]; W[j] = wn;
                    }
                    u64 s = fadd2(acc0, acc1);
                    float lo, hi;
                    upk2(s, lo, hi);
                    ys[k] = lo + hi;
                }
                yp[0] = make_float4(ys[0], ys[1], ys[2], ys[3]);
                yp[1] = make_float4(ys[4], ys[5], ys[6], ys[7]);
                c0 = n0; c1 = n1; xp = np; yp += 2;
            }
        }

        // ---- h from lane 31's final states: qr = a1/2,
        //      |qi| = sqrt(-a2 - qr^2) signed by qsign; h = p * S[L-1],
        //      S[L-1] = w[L-1] - conj(q) * w[L-2]. ----
        if (lane == 31) {
            float* hptr = out + (size_t)BB * DD * LL + (size_t)ch * NS * 2;
            #pragma unroll
            for (int j = 0; j < NP; j++) {
                float a1v[2], a2v[2], wv[2], wpv[2];
                upk2(A1[j], a1v[0], a1v[1]);
                upk2(A2[j], a2v[0], a2v[1]);
                upk2(W[j],  wv[0],  wv[1]);
                upk2(Wp[j], wpv[0], wpv[1]);
                #pragma unroll
                for (int h = 0; h < 2; h++) {
                    int n = 2 * j + h;
                    float qr = 0.5f * a1v[h];
                    float qi = __fsqrt_rn(fmaxf(fmaf(-qr, qr, -a2v[h]), 0.0f));
                    if (qsign & (1u << n)) qi = -qi;
                    float p  = sigm(alpha[d * NS + n]);
                    hptr[2 * n + 0] = p * fmaf(-qr, wpv[h], wv[h]);
                    hptr[2 * n + 1] = p * (qi * wpv[h]);
                }
            }
        }
    }
}

extern "C" void kernel_launch(void* const* d_in, const int* in_sizes, int n_in,
                              void* d_out, int out_size)
{
    const float* x     = (const float*)d_in[0];
    const float* alpha = (const float*)d_in[1];
    const float* delta = (const float*)d_in[2];
    const float* theta = (const float*)d_in[3];
    const float* gamma = (const float*)d_in[4];
    const float* omega = (const float*)d_in[5];
    float* out = (float*)d_out;

    reset_ctr_kernel<<<1, 1>>>();
    // Persistent grid: 4 CTAs/SM x 152 SMs; warps pull channels dynamically.
    cema_kernel<<<608, 128>>>(x, alpha, delta, theta, gamma, omega, out);
}